// round 2
// baseline (speedup 1.0000x reference)
#include <cuda_runtime.h>
#include <cuda_bf16.h>

// BPMLL loss, factorized:
//   inner[b]  = (sum_{t==0} exp(x)) * (sum_{t==1} exp(-x))
//   length[b] = n_pos * n_neg
//   out       = sum_b inner[b] / length[b]
//
// B = 128, L = 1024. target is int32 (JAX x64 disabled => int64 cast is a no-op).
// Single fused kernel: per-row blocks + last-block final reduction.

#define MAX_B 4096
__device__ float g_row_loss[MAX_B];
__device__ unsigned int g_arrive = 0;   // reset by last block each run

template<int BLOCK>
__global__ void bpmll_fused_kernel(const float* __restrict__ inp,
                                   const int* __restrict__ tgt,
                                   float* __restrict__ out,
                                   int L, int B) {
    const int b = blockIdx.x;
    const float4* __restrict__ x4 = (const float4*)(inp + (size_t)b * L);
    const int4*   __restrict__ t4 = (const int4*)(tgt + (size_t)b * L);
    const int nvec = L >> 2;   // 256 for L=1024

    float s_neg  = 0.0f;   // sum exp(x) over negatives
    float s_pinv = 0.0f;   // sum exp(-x) over positives
    float n_pos  = 0.0f;

    for (int i = threadIdx.x; i < nvec; i += BLOCK) {
        float4 v = x4[i];
        int4   t = t4[i];
        {
            bool p = (t.x == 1); float e = expf(p ? -v.x : v.x);
            s_pinv += p ? e : 0.0f; s_neg += p ? 0.0f : e; n_pos += p ? 1.0f : 0.0f;
        }
        {
            bool p = (t.y == 1); float e = expf(p ? -v.y : v.y);
            s_pinv += p ? e : 0.0f; s_neg += p ? 0.0f : e; n_pos += p ? 1.0f : 0.0f;
        }
        {
            bool p = (t.z == 1); float e = expf(p ? -v.z : v.z);
            s_pinv += p ? e : 0.0f; s_neg += p ? 0.0f : e; n_pos += p ? 1.0f : 0.0f;
        }
        {
            bool p = (t.w == 1); float e = expf(p ? -v.w : v.w);
            s_pinv += p ? e : 0.0f; s_neg += p ? 0.0f : e; n_pos += p ? 1.0f : 0.0f;
        }
    }

    // warp reduce
    #pragma unroll
    for (int off = 16; off > 0; off >>= 1) {
        s_neg  += __shfl_down_sync(0xffffffffu, s_neg,  off);
        s_pinv += __shfl_down_sync(0xffffffffu, s_pinv, off);
        n_pos  += __shfl_down_sync(0xffffffffu, n_pos,  off);
    }

    constexpr int NWARP = BLOCK / 32;
    __shared__ float sh_neg[NWARP], sh_pinv[NWARP], sh_np[NWARP];
    const int wid = threadIdx.x >> 5;
    const int lid = threadIdx.x & 31;
    if (lid == 0) { sh_neg[wid] = s_neg; sh_pinv[wid] = s_pinv; sh_np[wid] = n_pos; }
    __syncthreads();

    __shared__ bool amLast;
    if (threadIdx.x == 0) {
        float tn = 0.0f, tp = 0.0f, np = 0.0f;
        #pragma unroll
        for (int w = 0; w < NWARP; ++w) { tn += sh_neg[w]; tp += sh_pinv[w]; np += sh_np[w]; }
        float nn = (float)L - np;
        g_row_loss[b] = (tn * tp) / (np * nn);
        __threadfence();
        unsigned int prev = atomicAdd(&g_arrive, 1u);
        amLast = (prev == (unsigned int)(B - 1));
    }
    __syncthreads();

    if (amLast) {
        // deterministic final sum: fixed order, single block
        __shared__ float sh[BLOCK];
        float v = 0.0f;
        for (int i = threadIdx.x; i < B; i += BLOCK) v += g_row_loss[i];
        sh[threadIdx.x] = v;
        __syncthreads();
        #pragma unroll
        for (int s = BLOCK >> 1; s > 0; s >>= 1) {
            if (threadIdx.x < s) sh[threadIdx.x] += sh[threadIdx.x + s];
            __syncthreads();
        }
        if (threadIdx.x == 0) {
            out[0] = sh[0];
            g_arrive = 0;   // reset for next graph replay
        }
    }
}

extern "C" void kernel_launch(void* const* d_in, const int* in_sizes, int n_in,
                              void* d_out, int out_size) {
    const float* inp = (const float*)d_in[0];
    const int*   tgt = (const int*)d_in[1];
    float* out = (float*)d_out;

    const int B = 128;
    const int L = in_sizes[0] / B;   // 1024

    constexpr int BLOCK = 256;
    bpmll_fused_kernel<BLOCK><<<B, BLOCK>>>(inp, tgt, out, L, B);
}